// round 7
// baseline (speedup 1.0000x reference)
#include <cuda_runtime.h>
#include <cuda_bf16.h>
#include <mma.h>

using namespace nvcuda;

// ---------------- problem constants ----------------
#define BATCH 8
#define SEQ 4096
#define CTX_L 77
#define QDIM 1024
#define CDIM 768
#define HEADS 8
#define DHEAD 64
#define INNER 512          // HEADS * DHEAD

#define MX (BATCH * SEQ)     // 32768
#define MC (BATCH * CTX_L)   // 616

// ---------------- scratch (no runtime alloc allowed) ----------------
__device__ float g_Q[BATCH * SEQ * INNER];      // 64 MiB
__device__ float g_K[BATCH * CTX_L * INNER];    // ~1.2 MiB
__device__ float g_V[BATCH * CTX_L * INNER];
__device__ float g_A[BATCH * SEQ * INNER];      // 64 MiB  (attention output)

// ---------------- generic TF32 wmma GEMM body ----------------
// C[M,N] = A[M,K] @ B[K,N] (+ bias[n]); all row-major fp32.
// Requires: K % 32 == 0, N % 64 == 0. M arbitrary (bounds-checked).
#define GM_BM 64
#define GM_BN 64
#define GM_BK 32
#define GM_PADA 8   // As row stride 40
#define GM_PADB 8   // Bs row stride 72
#define GM_PADC 4   // Cs row stride 68

__device__ __forceinline__ void gemm_tf32_body(
    const float* __restrict__ A, const float* __restrict__ B,
    float* __restrict__ C, const float* __restrict__ bias,
    int M, int N, int K)
{
    __shared__ float As[GM_BM][GM_BK + GM_PADA];
    __shared__ float Bs[GM_BK][GM_BN + GM_PADB];
    __shared__ float Cs[GM_BM][GM_BN + GM_PADC];

    const int tid  = threadIdx.x;
    const int warp = tid >> 5;
    const int wm   = warp >> 1;   // 0..1
    const int wn   = warp & 1;    // 0..1
    const int row0 = blockIdx.y * GM_BM;
    const int col0 = blockIdx.x * GM_BN;

    wmma::fragment<wmma::accumulator, 16, 16, 8, float> acc[2][2];
#pragma unroll
    for (int i = 0; i < 2; i++)
#pragma unroll
        for (int j = 0; j < 2; j++)
            wmma::fill_fragment(acc[i][j], 0.0f);

    for (int k0 = 0; k0 < K; k0 += GM_BK) {
        // ---- load A tile 64x32 (512 float4 slots, 4 per thread) ----
#pragma unroll
        for (int i = 0; i < 4; i++) {
            int slot = tid + i * 128;
            int r  = slot >> 3;
            int c4 = (slot & 7) * 4;
            int grow = row0 + r;
            float4 v = make_float4(0.f, 0.f, 0.f, 0.f);
            if (grow < M)
                v = *(const float4*)(A + (size_t)grow * K + k0 + c4);
            *(float4*)&As[r][c4] = v;
        }
        // ---- load B tile 32x64 ----
#pragma unroll
        for (int i = 0; i < 4; i++) {
            int slot = tid + i * 128;
            int r  = slot >> 4;
            int c4 = (slot & 15) * 4;
            float4 v = *(const float4*)(B + (size_t)(k0 + r) * N + col0 + c4);
            *(float4*)&Bs[r][c4] = v;
        }
        __syncthreads();

#pragma unroll
        for (int kk = 0; kk < 4; kk++) {
            wmma::fragment<wmma::matrix_a, 16, 16, 8, wmma::precision::tf32, wmma::row_major> a0, a1;
            wmma::fragment<wmma::matrix_b, 16, 16, 8, wmma::precision::tf32, wmma::row_major> b0, b1;
            wmma::load_matrix_sync(a0, &As[wm * 32][kk * 8],      GM_BK + GM_PADA);
            wmma::load_matrix_sync(a1, &As[wm * 32 + 16][kk * 8], GM_BK + GM_PADA);
            wmma::load_matrix_sync(b0, &Bs[kk * 8][wn * 32],      GM_BN + GM_PADB);
            wmma::load_matrix_sync(b1, &Bs[kk * 8][wn * 32 + 16], GM_BN + GM_PADB);
#pragma unroll
            for (int t = 0; t < a0.num_elements; t++) {
                a0.x[t] = wmma::__float_to_tf32(a0.x[t]);
                a1.x[t] = wmma::__float_to_tf32(a1.x[t]);
            }
#pragma unroll
            for (int t = 0; t < b0.num_elements; t++) {
                b0.x[t] = wmma::__float_to_tf32(b0.x[t]);
                b1.x[t] = wmma::__float_to_tf32(b1.x[t]);
            }
            wmma::mma_sync(acc[0][0], a0, b0, acc[0][0]);
            wmma::mma_sync(acc[0][1], a0, b1, acc[0][1]);
            wmma::mma_sync(acc[1][0], a1, b0, acc[1][0]);
            wmma::mma_sync(acc[1][1], a1, b1, acc[1][1]);
        }
        __syncthreads();
    }

    // ---- epilogue via shared (bounds + bias) ----
#pragma unroll
    for (int i = 0; i < 2; i++)
#pragma unroll
        for (int j = 0; j < 2; j++)
            wmma::store_matrix_sync(&Cs[wm * 32 + i * 16][wn * 32 + j * 16],
                                    acc[i][j], GM_BN + GM_PADC, wmma::mem_row_major);
    __syncthreads();

#pragma unroll
    for (int i = 0; i < 8; i++) {
        int slot = tid + i * 128;
        int r  = slot >> 4;
        int c4 = (slot & 15) * 4;
        int grow = row0 + r;
        if (grow < M) {
            float4 v = *(const float4*)&Cs[r][c4];
            if (bias) {
                const float* bp = bias + col0 + c4;
                v.x += bp[0]; v.y += bp[1]; v.z += bp[2]; v.w += bp[3];
            }
            *(float4*)(C + (size_t)grow * N + col0 + c4) = v;
        }
    }
}

// ---------------- thin wrappers: scratch globals referenced in DEVICE code ----
__global__ __launch_bounds__(128) void gemm_q_kernel(
    const float* __restrict__ x, const float* __restrict__ Wq)
{
    gemm_tf32_body(x, Wq, g_Q, nullptr, MX, INNER, QDIM);
}

__global__ __launch_bounds__(128) void gemm_k_kernel(
    const float* __restrict__ ctx, const float* __restrict__ Wk)
{
    gemm_tf32_body(ctx, Wk, g_K, nullptr, MC, INNER, CDIM);
}

__global__ __launch_bounds__(128) void gemm_v_kernel(
    const float* __restrict__ ctx, const float* __restrict__ Wv)
{
    gemm_tf32_body(ctx, Wv, g_V, nullptr, MC, INNER, CDIM);
}

__global__ __launch_bounds__(128) void gemm_o_kernel(
    const float* __restrict__ Wo, const float* __restrict__ bo,
    float* __restrict__ out)
{
    gemm_tf32_body(g_A, Wo, out, bo, MX, QDIM, INNER);
}

// ---------------- fused cross-attention core ----------------
// One block = (b, h, 128 consecutive s rows). K,V staged in static SMEM
// (39.4 KB). One query row per thread; ONLINE softmax in registers.
__global__ __launch_bounds__(128) void attn_kernel()
{
    __shared__ float Ks[CTX_L * DHEAD];
    __shared__ float Vs[CTX_L * DHEAD];

    const int b = blockIdx.z;
    const int h = blockIdx.y;
    const int t = threadIdx.x;
    const int s = blockIdx.x * 128 + t;

    // stage K, V for this (b, h): layout in g_K/g_V is (B, L, INNER)
    for (int idx = t; idx < CTX_L * DHEAD; idx += 128) {
        int l = idx >> 6;
        int d = idx & 63;
        size_t g = ((size_t)(b * CTX_L + l)) * INNER + h * DHEAD + d;
        Ks[idx] = g_K[g];
        Vs[idx] = g_V[g];
    }
    __syncthreads();

    // load q row into registers
    const float* qp = g_Q + ((size_t)(b * SEQ + s)) * INNER + h * DHEAD;
    float q[DHEAD];
#pragma unroll
    for (int i = 0; i < DHEAD / 4; i++) {
        float4 v = *(const float4*)(qp + i * 4);
        q[4 * i + 0] = v.x; q[4 * i + 1] = v.y;
        q[4 * i + 2] = v.z; q[4 * i + 3] = v.w;
    }

    const float scale = 0.125f;  // 64^-0.5
    float m = -INFINITY;
    float sum = 0.f;
    float acc[DHEAD];
#pragma unroll
    for (int d = 0; d < DHEAD; d++) acc[d] = 0.f;

    for (int l = 0; l < CTX_L; l++) {
        float dot = 0.f;
#pragma unroll
        for (int d = 0; d < DHEAD; d += 4) {
            float4 kv = *(const float4*)&Ks[l * DHEAD + d];
            dot += q[d] * kv.x + q[d + 1] * kv.y + q[d + 2] * kv.z + q[d + 3] * kv.w;
        }
        dot *= scale;

        if (dot > m) {
            float r = __expf(m - dot);   // rescale old state
            sum *= r;
#pragma unroll
            for (int d = 0; d < DHEAD; d++) acc[d] *= r;
            m = dot;
        }
        float e = __expf(dot - m);
        sum += e;
#pragma unroll
        for (int d = 0; d < DHEAD; d += 4) {
            float4 vv = *(const float4*)&Vs[l * DHEAD + d];
            acc[d + 0] += e * vv.x;
            acc[d + 1] += e * vv.y;
            acc[d + 2] += e * vv.z;
            acc[d + 3] += e * vv.w;
        }
    }

    const float inv = 1.f / sum;
    float* op = g_A + ((size_t)(b * SEQ + s)) * INNER + h * DHEAD;
#pragma unroll
    for (int i = 0; i < DHEAD / 4; i++) {
        float4 v = make_float4(acc[4 * i] * inv, acc[4 * i + 1] * inv,
                               acc[4 * i + 2] * inv, acc[4 * i + 3] * inv);
        *(float4*)(op + i * 4) = v;
    }
}

// ---------------- launch: ONLY kernel launches, nothing else ----------------
extern "C" void kernel_launch(void* const* d_in, const int* in_sizes, int n_in,
                              void* d_out, int out_size)
{
    const float* x       = (const float*)d_in[0];
    const float* context = (const float*)d_in[1];
    const float* Wq      = (const float*)d_in[2];
    const float* Wk      = (const float*)d_in[3];
    const float* Wv      = (const float*)d_in[4];
    const float* Wo      = (const float*)d_in[5];
    const float* bo      = (const float*)d_in[6];
    float* out = (float*)d_out;

    // Q = x @ Wq : (32768,1024) @ (1024,512)
    gemm_q_kernel<<<dim3(INNER / GM_BN, MX / GM_BM), 128>>>(x, Wq);
    // K = context @ Wk : (616,768) @ (768,512)
    gemm_k_kernel<<<dim3(INNER / GM_BN, (MC + GM_BM - 1) / GM_BM), 128>>>(context, Wk);
    // V = context @ Wv
    gemm_v_kernel<<<dim3(INNER / GM_BN, (MC + GM_BM - 1) / GM_BM), 128>>>(context, Wv);
    // attention (static 39.4 KB smem)
    attn_kernel<<<dim3(SEQ / 128, HEADS, BATCH), 128>>>();
    // out = A @ Wo + bo : (32768,512) @ (512,1024)
    gemm_o_kernel<<<dim3(QDIM / GM_BN, MX / GM_BM), 128>>>(Wo, bo, out);
}

// round 11
// speedup vs baseline: 1.0200x; 1.0200x over previous
#include <cuda_runtime.h>
#include <cuda_bf16.h>
#include <mma.h>

using namespace nvcuda;

// ---------------- problem constants ----------------
#define BATCH 8
#define SEQ 4096
#define CTX_L 77
#define QDIM 1024
#define CDIM 768
#define HEADS 8
#define DHEAD 64
#define INNER 512          // HEADS * DHEAD

#define MX (BATCH * SEQ)     // 32768
#define MC (BATCH * CTX_L)   // 616

// ---------------- scratch (no runtime alloc allowed) ----------------
__device__ float g_Q[BATCH * SEQ * INNER];      // 64 MiB
__device__ float g_K[BATCH * CTX_L * INNER];
__device__ float g_V[BATCH * CTX_L * INNER];
__device__ float g_A[BATCH * SEQ * INNER];      // 64 MiB

// ---------------- cp.async helpers ----------------
__device__ __forceinline__ unsigned smem_u32(const void* p) {
    return (unsigned)__cvta_generic_to_shared(p);
}
__device__ __forceinline__ void cp16(unsigned s, const void* g) {
    asm volatile("cp.async.cg.shared.global [%0], [%1], 16;\n" :: "r"(s), "l"(g));
}

// =====================================================================
// FAST GEMM: C[M,N] = A[M,K] @ B[K,N] (+bias). Requires M%128==0,
// N%128==0, K%16==0. 128x128x16 tiles, 256 threads, cp.async 2-stage.
// =====================================================================
#define FBM 128
#define FBN 128
#define FBK 16
#define FLDA 24    // FBK + 8 pad -> 96B row stride (32B multiple)
#define FLDB 136   // FBN + 8 pad -> 544B row stride (32B multiple)

__device__ __forceinline__ void gemm_fast_body(
    const float* __restrict__ A, const float* __restrict__ B,
    float* __restrict__ C, const float* __restrict__ bias,
    int M, int N, int K)
{
    __shared__ float As[2][FBM][FLDA];
    __shared__ float Bs[2][FBK][FLDB];

    const int tid  = threadIdx.x;
    const int warp = tid >> 5;
    const int wm   = warp >> 1;   // 0..3
    const int wn   = warp & 1;    // 0..1
    const int row0 = blockIdx.y * FBM;
    const int col0 = blockIdx.x * FBN;

    wmma::fragment<wmma::accumulator, 16, 16, 8, float> acc[2][4];
    if (bias) {
        // replicate bias slice into 16 rows of Bs[0], load as accumulator init
        for (int i = tid; i < 16 * FBN; i += 256) {
            int r = i >> 7, c = i & 127;
            Bs[0][r][c] = bias[col0 + c];
        }
        __syncthreads();
#pragma unroll
        for (int i = 0; i < 2; i++)
#pragma unroll
            for (int j = 0; j < 4; j++)
                wmma::load_matrix_sync(acc[i][j], &Bs[0][0][wn * 64 + j * 16],
                                       FLDB, wmma::mem_row_major);
        __syncthreads();
    } else {
#pragma unroll
        for (int i = 0; i < 2; i++)
#pragma unroll
            for (int j = 0; j < 4; j++)
                wmma::fill_fragment(acc[i][j], 0.0f);
    }

    auto load_stage = [&](int st, int k0) {
#pragma unroll
        for (int i = 0; i < 2; i++) {             // A: 128x16 = 512 float4
            int slot = tid + i * 256;
            int r = slot >> 2, c4 = (slot & 3) * 4;
            cp16(smem_u32(&As[st][r][c4]),
                 A + (size_t)(row0 + r) * K + k0 + c4);
        }
#pragma unroll
        for (int i = 0; i < 2; i++) {             // B: 16x128 = 512 float4
            int slot = tid + i * 256;
            int r = slot >> 5, c4 = (slot & 31) * 4;
            cp16(smem_u32(&Bs[st][r][c4]),
                 B + (size_t)(k0 + r) * N + col0 + c4);
        }
        asm volatile("cp.async.commit_group;" ::: "memory");
    };

    const int nIter = K / FBK;
    load_stage(0, 0);

    for (int it = 0; it < nIter; ++it) {
        const int st = it & 1;
        if (it + 1 < nIter) {
            load_stage(st ^ 1, (it + 1) * FBK);
            asm volatile("cp.async.wait_group 1;" ::: "memory");
        } else {
            asm volatile("cp.async.wait_group 0;" ::: "memory");
        }
        __syncthreads();

#pragma unroll
        for (int kk = 0; kk < 2; kk++) {
            wmma::fragment<wmma::matrix_a, 16, 16, 8, wmma::precision::tf32, wmma::row_major> af[2];
            wmma::fragment<wmma::matrix_b, 16, 16, 8, wmma::precision::tf32, wmma::row_major> bf[4];
            wmma::load_matrix_sync(af[0], &As[st][wm * 32][kk * 8],      FLDA);
            wmma::load_matrix_sync(af[1], &As[st][wm * 32 + 16][kk * 8], FLDA);
#pragma unroll
            for (int j = 0; j < 4; j++)
                wmma::load_matrix_sync(bf[j], &Bs[st][kk * 8][wn * 64 + j * 16], FLDB);
#pragma unroll
            for (int i = 0; i < 2; i++)
#pragma unroll
                for (int t = 0; t < af[0].num_elements; t++)
                    af[i].x[t] = wmma::__float_to_tf32(af[i].x[t]);
#pragma unroll
            for (int j = 0; j < 4; j++)
#pragma unroll
                for (int t = 0; t < bf[0].num_elements; t++)
                    bf[j].x[t] = wmma::__float_to_tf32(bf[j].x[t]);
#pragma unroll
            for (int i = 0; i < 2; i++)
#pragma unroll
                for (int j = 0; j < 4; j++)
                    wmma::mma_sync(acc[i][j], af[i], bf[j], acc[i][j]);
        }
        __syncthreads();
    }

    // epilogue: fragments straight to GMEM (row-major, ldm=N)
#pragma unroll
    for (int i = 0; i < 2; i++)
#pragma unroll
        for (int j = 0; j < 4; j++)
            wmma::store_matrix_sync(
                C + (size_t)(row0 + wm * 32 + i * 16) * N + col0 + wn * 64 + j * 16,
                acc[i][j], N, wmma::mem_row_major);
}

__global__ __launch_bounds__(256) void gemm_q_fast(
    const float* __restrict__ x, const float* __restrict__ Wq)
{
    gemm_fast_body(x, Wq, g_Q, nullptr, MX, INNER, QDIM);
}
__global__ __launch_bounds__(256) void gemm_o_fast(
    const float* __restrict__ Wo, const float* __restrict__ bo,
    float* __restrict__ out)
{
    gemm_fast_body(g_A, Wo, out, bo, MX, QDIM, INNER);
}

// =====================================================================
// small GEMM (K/V projections, M=616): 64x64x32, 128 threads, bounds.
// =====================================================================
#define GM_BM 64
#define GM_BN 64
#define GM_BK 32
#define GM_PADA 8
#define GM_PADB 8

__device__ __forceinline__ void gemm_small_body(
    const float* __restrict__ A, const float* __restrict__ B,
    float* __restrict__ C, int M, int N, int K)
{
    __shared__ float As[GM_BM][GM_BK + GM_PADA];
    __shared__ float Bs[GM_BK][GM_BN + GM_PADB];
    __shared__ float Cs[GM_BM][GM_BN + 4];

    const int tid  = threadIdx.x;
    const int warp = tid >> 5;
    const int wm   = warp >> 1;
    const int wn   = warp & 1;
    const int row0 = blockIdx.y * GM_BM;
    const int col0 = blockIdx.x * GM_BN;

    wmma::fragment<wmma::accumulator, 16, 16, 8, float> acc[2][2];
#pragma unroll
    for (int i = 0; i < 2; i++)
#pragma unroll
        for (int j = 0; j < 2; j++)
            wmma::fill_fragment(acc[i][j], 0.0f);

    for (int k0 = 0; k0 < K; k0 += GM_BK) {
#pragma unroll
        for (int i = 0; i < 4; i++) {
            int slot = tid + i * 128;
            int r = slot >> 3, c4 = (slot & 7) * 4;
            int grow = row0 + r;
            float4 v = make_float4(0.f, 0.f, 0.f, 0.f);
            if (grow < M)
                v = *(const float4*)(A + (size_t)grow * K + k0 + c4);
            *(float4*)&As[r][c4] = v;
        }
#pragma unroll
        for (int i = 0; i < 4; i++) {
            int slot = tid + i * 128;
            int r = slot >> 4, c4 = (slot & 15) * 4;
            float4 v = *(const float4*)(B + (size_t)(k0 + r) * N + col0 + c4);
            *(float4*)&Bs[r][c4] = v;
        }
        __syncthreads();

#pragma unroll
        for (int kk = 0; kk < 4; kk++) {
            wmma::fragment<wmma::matrix_a, 16, 16, 8, wmma::precision::tf32, wmma::row_major> a0, a1;
            wmma::fragment<wmma::matrix_b, 16, 16, 8, wmma::precision::tf32, wmma::row_major> b0, b1;
            wmma::load_matrix_sync(a0, &As[wm * 32][kk * 8],      GM_BK + GM_PADA);
            wmma::load_matrix_sync(a1, &As[wm * 32 + 16][kk * 8], GM_BK + GM_PADA);
            wmma::load_matrix_sync(b0, &Bs[kk * 8][wn * 32],      GM_BN + GM_PADB);
            wmma::load_matrix_sync(b1, &Bs[kk * 8][wn * 32 + 16], GM_BN + GM_PADB);
#pragma unroll
            for (int t = 0; t < a0.num_elements; t++) {
                a0.x[t] = wmma::__float_to_tf32(a0.x[t]);
                a1.x[t] = wmma::__float_to_tf32(a1.x[t]);
            }
#pragma unroll
            for (int t = 0; t < b0.num_elements; t++) {
                b0.x[t] = wmma::__float_to_tf32(b0.x[t]);
                b1.x[t] = wmma::__float_to_tf32(b1.x[t]);
            }
            wmma::mma_sync(acc[0][0], a0, b0, acc[0][0]);
            wmma::mma_sync(acc[0][1], a0, b1, acc[0][1]);
            wmma::mma_sync(acc[1][0], a1, b0, acc[1][0]);
            wmma::mma_sync(acc[1][1], a1, b1, acc[1][1]);
        }
        __syncthreads();
    }

#pragma unroll
    for (int i = 0; i < 2; i++)
#pragma unroll
        for (int j = 0; j < 2; j++)
            wmma::store_matrix_sync(&Cs[wm * 32 + i * 16][wn * 32 + j * 16],
                                    acc[i][j], GM_BN + 4, wmma::mem_row_major);
    __syncthreads();

#pragma unroll
    for (int i = 0; i < 8; i++) {
        int slot = tid + i * 128;
        int r = slot >> 4, c4 = (slot & 15) * 4;
        int grow = row0 + r;
        if (grow < M)
            *(float4*)(C + (size_t)grow * N + col0 + c4) = *(float4*)&Cs[r][c4];
    }
}

__global__ __launch_bounds__(128) void gemm_k_kernel(
    const float* __restrict__ ctx, const float* __restrict__ Wk)
{
    gemm_small_body(ctx, Wk, g_K, MC, INNER, CDIM);
}
__global__ __launch_bounds__(128) void gemm_v_kernel(
    const float* __restrict__ ctx, const float* __restrict__ Wv)
{
    gemm_small_body(ctx, Wv, g_V, MC, INNER, CDIM);
}

// =====================================================================
// fused cross-attention: block = (b, h, 128 s-rows), 256 threads.
// Lane pair (2t, 2t+1) shares one query row; each handles 32 of 64 dims.
// Online softmax; dot halves combined via shfl_xor(1).
// =====================================================================
__global__ __launch_bounds__(256) void attn_kernel()
{
    __shared__ float Ks[CTX_L * DHEAD];
    __shared__ float Vs[CTX_L * DHEAD];

    const int b = blockIdx.z;
    const int h = blockIdx.y;
    const int t = threadIdx.x;
    const int qrow = t >> 1;        // 0..127
    const int half = t & 1;         // 0..1
    const int s = blockIdx.x * 128 + qrow;

    for (int idx = t; idx < CTX_L * DHEAD; idx += 256) {
        int l = idx >> 6;
        int d = idx & 63;
        size_t g = ((size_t)(b * CTX_L + l)) * INNER + h * DHEAD + d;
        Ks[idx] = g_K[g];
        Vs[idx] = g_V[g];
    }
    __syncthreads();

    const float* qp = g_Q + ((size_t)(b * SEQ + s)) * INNER + h * DHEAD + half * 32;
    float q[32];
#pragma unroll
    for (int i = 0; i < 8; i++) {
        float4 v = *(const float4*)(qp + i * 4);
        q[4 * i + 0] = v.x; q[4 * i + 1] = v.y;
        q[4 * i + 2] = v.z; q[4 * i + 3] = v.w;
    }

    const float scale = 0.125f;
    float m = -INFINITY;
    float sum = 0.f;
    float acc[32];
#pragma unroll
    for (int d = 0; d < 32; d++) acc[d] = 0.f;

    for (int l = 0; l < CTX_L; l++) {
        const float* kp = &Ks[l * DHEAD + half * 32];
        float part = 0.f;
#pragma unroll
        for (int d = 0; d < 32; d += 4) {
            float4 kv = *(const float4*)(kp + d);
            part += q[d] * kv.x + q[d + 1] * kv.y + q[d + 2] * kv.z + q[d + 3] * kv.w;
        }
        float dot = (part + __shfl_xor_sync(0xffffffffu, part, 1)) * scale;

        if (dot > m) {
            float r = __expf(m - dot);
            sum *= r;
#pragma unroll
            for (int d = 0; d < 32; d++) acc[d] *= r;
            m = dot;
        }
        float e = __expf(dot - m);
        sum += e;
        const float* vp = &Vs[l * DHEAD + half * 32];
#pragma unroll
        for (int d = 0; d < 32; d += 4) {
            float4 vv = *(const float4*)(vp + d);
            acc[d + 0] += e * vv.x;
            acc[d + 1] += e * vv.y;
            acc[d + 2] += e * vv.z;
            acc[d + 3] += e * vv.w;
        }
    }

    const float inv = 1.f / sum;
    float* op = g_A + ((size_t)(b * SEQ + s)) * INNER + h * DHEAD + half * 32;
#pragma unroll
    for (int i = 0; i < 8; i++) {
        float4 v = make_float4(acc[4 * i] * inv, acc[4 * i + 1] * inv,
                               acc[4 * i + 2] * inv, acc[4 * i + 3] * inv);
        *(float4*)(op + i * 4) = v;
    }
}

// ---------------- launch: ONLY kernel launches ----------------
extern "C" void kernel_launch(void* const* d_in, const int* in_sizes, int n_in,
                              void* d_out, int out_size)
{
    const float* x       = (const float*)d_in[0];
    const float* context = (const float*)d_in[1];
    const float* Wq      = (const float*)d_in[2];
    const float* Wk      = (const float*)d_in[3];
    const float* Wv      = (const float*)d_in[4];
    const float* Wo      = (const float*)d_in[5];
    const float* bo      = (const float*)d_in[6];
    float* out = (float*)d_out;

    // Q = x @ Wq : (32768,1024)@(1024,512), fast path
    gemm_q_fast<<<dim3(INNER / FBN, MX / FBM), 256>>>(x, Wq);
    // K,V = context @ Wk/Wv : (616,768)@(768,512), small path
    gemm_k_kernel<<<dim3(INNER / GM_BN, (MC + GM_BM - 1) / GM_BM), 128>>>(context, Wk);
    gemm_v_kernel<<<dim3(INNER / GM_BN, (MC + GM_BM - 1) / GM_BM), 128>>>(context, Wv);
    // attention
    attn_kernel<<<dim3(SEQ / 128, HEADS, BATCH), 256>>>();
    // out = A @ Wo + bo : (32768,512)@(512,1024), fast path
    gemm_o_fast<<<dim3(QDIM / FBN, MX / FBM), 256>>>(Wo, bo, out);
}

// round 12
// speedup vs baseline: 1.1135x; 1.0916x over previous
#include <cuda_runtime.h>
#include <cuda_bf16.h>
#include <mma.h>

using namespace nvcuda;

// ---------------- problem constants ----------------
#define BATCH 8
#define SEQ 4096
#define CTX_L 77
#define QDIM 1024
#define CDIM 768
#define HEADS 8
#define DHEAD 64
#define INNER 512          // HEADS * DHEAD

#define MX (BATCH * SEQ)     // 32768
#define MC (BATCH * CTX_L)   // 616

// ---------------- scratch (no runtime alloc allowed) ----------------
__device__ float g_Q[BATCH * SEQ * INNER];      // 64 MiB
__device__ float g_K[BATCH * CTX_L * INNER];
__device__ float g_V[BATCH * CTX_L * INNER];
__device__ float g_A[BATCH * SEQ * INNER];      // 64 MiB

// ---------------- cp.async helpers ----------------
__device__ __forceinline__ unsigned smem_u32(const void* p) {
    return (unsigned)__cvta_generic_to_shared(p);
}
__device__ __forceinline__ void cp16(unsigned s, const void* g) {
    asm volatile("cp.async.cg.shared.global [%0], [%1], 16;\n" :: "r"(s), "l"(g));
}
#define CP_COMMIT() asm volatile("cp.async.commit_group;" ::: "memory")
#define CP_WAIT(n)  asm volatile("cp.async.wait_group %0;" :: "n"(n) : "memory")

// =====================================================================
// FAST GEMM: C[M,N] = A[M,K] @ B[K,N] (+bias). Requires M%128==0,
// N%128==0, K%16==0, K/16 >= 3. 128x128x16 tiles, 256 threads,
// cp.async 3-stage multistage (ONE __syncthreads per iteration).
// Dynamic smem: 3*(128*20 + 16*132)*4 = 56064 bytes.
// =====================================================================
#define FBM 128
#define FBN 128
#define FBK 16
#define ALD 20     // A row stride (80B: 16B multiple, rotates banks)
#define BLD 132    // B row stride (528B: 16B multiple, rotates banks)
#define A_STAGE (FBM * ALD)   // 2560 floats
#define B_STAGE (FBK * BLD)   // 2112 floats
#define GEMM_SMEM_BYTES ((3 * (A_STAGE + B_STAGE)) * 4)  // 56064

__device__ __forceinline__ void gemm_fast_body(
    const float* __restrict__ A, const float* __restrict__ B,
    float* __restrict__ C, const float* __restrict__ bias,
    int M, int N, int K)
{
    extern __shared__ float dsm[];
    float* As = dsm;                 // [3][128][ALD]
    float* Bs = dsm + 3 * A_STAGE;   // [3][16][BLD]

    const int tid  = threadIdx.x;
    const int warp = tid >> 5;
    const int wm   = warp >> 1;   // 0..3
    const int wn   = warp & 1;    // 0..1
    const int row0 = blockIdx.y * FBM;
    const int col0 = blockIdx.x * FBN;

    wmma::fragment<wmma::accumulator, 16, 16, 8, float> acc[2][4];
    if (bias) {
        // replicate bias into 16 rows of Bs stage 0, load as acc init
        for (int i = tid; i < 16 * FBN; i += 256) {
            int r = i >> 7, c = i & 127;
            Bs[r * BLD + c] = bias[col0 + c];
        }
        __syncthreads();
#pragma unroll
        for (int i = 0; i < 2; i++)
#pragma unroll
            for (int j = 0; j < 4; j++)
                wmma::load_matrix_sync(acc[i][j], &Bs[wn * 64 + j * 16],
                                       BLD, wmma::mem_row_major);
        __syncthreads();
    } else {
#pragma unroll
        for (int i = 0; i < 2; i++)
#pragma unroll
            for (int j = 0; j < 4; j++)
                wmma::fill_fragment(acc[i][j], 0.0f);
    }

    auto load_stage = [&](int st, int k0) {
        float* Ad = As + st * A_STAGE;
        float* Bd = Bs + st * B_STAGE;
#pragma unroll
        for (int i = 0; i < 2; i++) {             // A: 128x16 = 512 float4
            int slot = tid + i * 256;
            int r = slot >> 2, c4 = (slot & 3) * 4;
            cp16(smem_u32(&Ad[r * ALD + c4]),
                 A + (size_t)(row0 + r) * K + k0 + c4);
        }
#pragma unroll
        for (int i = 0; i < 2; i++) {             // B: 16x128 = 512 float4
            int slot = tid + i * 256;
            int r = slot >> 5, c4 = (slot & 31) * 4;
            cp16(smem_u32(&Bd[r * BLD + c4]),
                 B + (size_t)(k0 + r) * N + col0 + c4);
        }
        CP_COMMIT();
    };

    const int nIter = K / FBK;
    load_stage(0, 0);
    load_stage(1, FBK);

    int st = 0;
    for (int it = 0; it < nIter; ++it) {
        if (it == nIter - 1) { CP_WAIT(0); } else { CP_WAIT(1); }
        __syncthreads();   // all warps done with stage (it-1)%3 == load target
        if (it + 2 < nIter) {
            int tgt = st + 2; if (tgt >= 3) tgt -= 3;
            load_stage(tgt, (it + 2) * FBK);
        }

        const float* Ab = As + st * A_STAGE;
        const float* Bb = Bs + st * B_STAGE;
#pragma unroll
        for (int kk = 0; kk < 2; kk++) {
            wmma::fragment<wmma::matrix_a, 16, 16, 8, wmma::precision::tf32, wmma::row_major> af[2];
            wmma::fragment<wmma::matrix_b, 16, 16, 8, wmma::precision::tf32, wmma::row_major> bf[4];
            wmma::load_matrix_sync(af[0], &Ab[(wm * 32) * ALD + kk * 8],      ALD);
            wmma::load_matrix_sync(af[1], &Ab[(wm * 32 + 16) * ALD + kk * 8], ALD);
#pragma unroll
            for (int j = 0; j < 4; j++)
                wmma::load_matrix_sync(bf[j], &Bb[(kk * 8) * BLD + wn * 64 + j * 16], BLD);
#pragma unroll
            for (int i = 0; i < 2; i++)
#pragma unroll
                for (int t = 0; t < af[0].num_elements; t++)
                    af[i].x[t] = wmma::__float_to_tf32(af[i].x[t]);
#pragma unroll
            for (int j = 0; j < 4; j++)
#pragma unroll
                for (int t = 0; t < bf[0].num_elements; t++)
                    bf[j].x[t] = wmma::__float_to_tf32(bf[j].x[t]);
#pragma unroll
            for (int i = 0; i < 2; i++)
#pragma unroll
                for (int j = 0; j < 4; j++)
                    wmma::mma_sync(acc[i][j], af[i], bf[j], acc[i][j]);
        }
        if (++st == 3) st = 0;
    }

    // epilogue: fragments straight to GMEM
#pragma unroll
    for (int i = 0; i < 2; i++)
#pragma unroll
        for (int j = 0; j < 4; j++)
            wmma::store_matrix_sync(
                C + (size_t)(row0 + wm * 32 + i * 16) * N + col0 + wn * 64 + j * 16,
                acc[i][j], N, wmma::mem_row_major);
}

__global__ __launch_bounds__(256) void gemm_q_fast(
    const float* __restrict__ x, const float* __restrict__ Wq)
{
    gemm_fast_body(x, Wq, g_Q, nullptr, MX, INNER, QDIM);
}
__global__ __launch_bounds__(256) void gemm_o_fast(
    const float* __restrict__ Wo, const float* __restrict__ bo,
    float* __restrict__ out)
{
    gemm_fast_body(g_A, Wo, out, bo, MX, QDIM, INNER);
}

// =====================================================================
// small GEMM (K/V projections, M=616): 64x64x32, 128 threads, bounds.
// =====================================================================
#define GM_BM 64
#define GM_BN 64
#define GM_BK 32
#define GM_PADA 8
#define GM_PADB 8

__device__ __forceinline__ void gemm_small_body(
    const float* __restrict__ A, const float* __restrict__ B,
    float* __restrict__ C, int M, int N, int K)
{
    __shared__ float As[GM_BM][GM_BK + GM_PADA];
    __shared__ float Bs[GM_BK][GM_BN + GM_PADB];
    __shared__ float Cs[GM_BM][GM_BN + 4];

    const int tid  = threadIdx.x;
    const int warp = tid >> 5;
    const int wm   = warp >> 1;
    const int wn   = warp & 1;
    const int row0 = blockIdx.y * GM_BM;
    const int col0 = blockIdx.x * GM_BN;

    wmma::fragment<wmma::accumulator, 16, 16, 8, float> acc[2][2];
#pragma unroll
    for (int i = 0; i < 2; i++)
#pragma unroll
        for (int j = 0; j < 2; j++)
            wmma::fill_fragment(acc[i][j], 0.0f);

    for (int k0 = 0; k0 < K; k0 += GM_BK) {
#pragma unroll
        for (int i = 0; i < 4; i++) {
            int slot = tid + i * 128;
            int r = slot >> 3, c4 = (slot & 7) * 4;
            int grow = row0 + r;
            float4 v = make_float4(0.f, 0.f, 0.f, 0.f);
            if (grow < M)
                v = *(const float4*)(A + (size_t)grow * K + k0 + c4);
            *(float4*)&As[r][c4] = v;
        }
#pragma unroll
        for (int i = 0; i < 4; i++) {
            int slot = tid + i * 128;
            int r = slot >> 4, c4 = (slot & 15) * 4;
            float4 v = *(const float4*)(B + (size_t)(k0 + r) * N + col0 + c4);
            *(float4*)&Bs[r][c4] = v;
        }
        __syncthreads();

#pragma unroll
        for (int kk = 0; kk < 4; kk++) {
            wmma::fragment<wmma::matrix_a, 16, 16, 8, wmma::precision::tf32, wmma::row_major> a0, a1;
            wmma::fragment<wmma::matrix_b, 16, 16, 8, wmma::precision::tf32, wmma::row_major> b0, b1;
            wmma::load_matrix_sync(a0, &As[wm * 32][kk * 8],      GM_BK + GM_PADA);
            wmma::load_matrix_sync(a1, &As[wm * 32 + 16][kk * 8], GM_BK + GM_PADA);
            wmma::load_matrix_sync(b0, &Bs[kk * 8][wn * 32],      GM_BN + GM_PADB);
            wmma::load_matrix_sync(b1, &Bs[kk * 8][wn * 32 + 16], GM_BN + GM_PADB);
#pragma unroll
            for (int t = 0; t < a0.num_elements; t++) {
                a0.x[t] = wmma::__float_to_tf32(a0.x[t]);
                a1.x[t] = wmma::__float_to_tf32(a1.x[t]);
            }
#pragma unroll
            for (int t = 0; t < b0.num_elements; t++) {
                b0.x[t] = wmma::__float_to_tf32(b0.x[t]);
                b1.x[t] = wmma::__float_to_tf32(b1.x[t]);
            }
            wmma::mma_sync(acc[0][0], a0, b0, acc[0][0]);
            wmma::mma_sync(acc[0][1], a0, b1, acc[0][1]);
            wmma::mma_sync(acc[1][0], a1, b0, acc[1][0]);
            wmma::mma_sync(acc[1][1], a1, b1, acc[1][1]);
        }
        __syncthreads();
    }

#pragma unroll
    for (int i = 0; i < 2; i++)
#pragma unroll
        for (int j = 0; j < 2; j++)
            wmma::store_matrix_sync(&Cs[wm * 32 + i * 16][wn * 32 + j * 16],
                                    acc[i][j], GM_BN + 4, wmma::mem_row_major);
    __syncthreads();

#pragma unroll
    for (int i = 0; i < 8; i++) {
        int slot = tid + i * 128;
        int r = slot >> 4, c4 = (slot & 15) * 4;
        int grow = row0 + r;
        if (grow < M)
            *(float4*)(C + (size_t)grow * N + col0 + c4) = *(float4*)&Cs[r][c4];
    }
}

__global__ __launch_bounds__(128) void gemm_k_kernel(
    const float* __restrict__ ctx, const float* __restrict__ Wk)
{
    gemm_small_body(ctx, Wk, g_K, MC, INNER, CDIM);
}
__global__ __launch_bounds__(128) void gemm_v_kernel(
    const float* __restrict__ ctx, const float* __restrict__ Wv)
{
    gemm_small_body(ctx, Wv, g_V, MC, INNER, CDIM);
}

// =====================================================================
// Tensor-core cross-attention. Block = (b, h, 64 q-rows), 256 threads.
// Phase 1: S = Q @ K^T via tf32 wmma (K rows padded to 96, cols 80-95
//          never computed). Phase 2: softmax (4 thr/row, shfl reduce),
//          writes P (prescaled by 1/sum), zeros for l >= 77.
// Phase 3: O = P @ V via tf32 wmma, V staged in two 32-col chunks
//          (pad rows zeroed -> no NaN from 0*garbage).
// Smem phases overlap inside one 43520-byte static buffer.
// =====================================================================
#define BQ   64
#define LPAD 96
#define QLD  68    // Q/K row stride (272B = 17*16, rotates banks)
#define SLD  100   // S row stride (400B)
#define VLD  36    // V row stride (144B)

__global__ __launch_bounds__(256) void attn_wmma_kernel()
{
    __shared__ float sm[10880];           // 43520 B
    float* Qs = sm;                       // [64][QLD]   phase 1
    float* Ks = sm + BQ * QLD;            // [96][QLD]   phase 1 (rows>=77 garbage, ok)
    float* Ss = sm;                       // [64][SLD]   phase 2+ (overlaps Qs/Ks head)
    float* Vs = sm + BQ * SLD;            // [96][VLD]   phase 3  (overlaps Ks tail)

    const int b  = blockIdx.z;
    const int h  = blockIdx.y;
    const int s0 = blockIdx.x * BQ;
    const int tid  = threadIdx.x;
    const int warp = tid >> 5;
    const int wr   = warp >> 1;   // 0..3 row strip (16 rows)
    const int wc   = warp & 1;    // 0..1

    // ---- stage Q (64x64) and K (77x64) ----
    for (int idx = tid; idx < BQ * 16; idx += 256) {
        int r = idx >> 4, c4 = (idx & 15) << 2;
        *(float4*)&Qs[r * QLD + c4] =
            *(const float4*)&g_Q[((size_t)(b * SEQ + s0 + r)) * INNER + h * DHEAD + c4];
    }
    for (int idx = tid; idx < CTX_L * 16; idx += 256) {
        int r = idx >> 4, c4 = (idx & 15) << 2;
        *(float4*)&Ks[r * QLD + c4] =
            *(const float4*)&g_K[((size_t)(b * CTX_L + r)) * INNER + h * DHEAD + c4];
    }
    __syncthreads();

    // ---- phase 1: S = Q @ K^T  (warp wc=0: col tiles 0..2, wc=1: 3..4) ----
    const int ct0 = wc ? 3 : 0;
    const int nct = wc ? 2 : 3;
    wmma::fragment<wmma::accumulator, 16, 16, 8, float> sacc[3];
#pragma unroll
    for (int j = 0; j < 3; j++) wmma::fill_fragment(sacc[j], 0.0f);

#pragma unroll
    for (int k = 0; k < 8; k++) {
        wmma::fragment<wmma::matrix_a, 16, 16, 8, wmma::precision::tf32, wmma::row_major> af;
        wmma::load_matrix_sync(af, &Qs[(wr * 16) * QLD + k * 8], QLD);
#pragma unroll
        for (int t = 0; t < af.num_elements; t++) af.x[t] = wmma::__float_to_tf32(af.x[t]);
#pragma unroll
        for (int j = 0; j < 3; j++) {
            if (j >= nct) break;
            wmma::fragment<wmma::matrix_b, 16, 16, 8, wmma::precision::tf32, wmma::col_major> bf;
            wmma::load_matrix_sync(bf, &Ks[((ct0 + j) * 16) * QLD + k * 8], QLD);
#pragma unroll
            for (int t = 0; t < bf.num_elements; t++) bf.x[t] = wmma::__float_to_tf32(bf.x[t]);
            wmma::mma_sync(sacc[j], af, bf, sacc[j]);
        }
    }
    // scale by 1/sqrt(64)
#pragma unroll
    for (int j = 0; j < 3; j++)
#pragma unroll
        for (int t = 0; t < sacc[j].num_elements; t++) sacc[j].x[t] *= 0.125f;

    __syncthreads();   // everyone done reading Qs/Ks before Ss overwrites them
#pragma unroll
    for (int j = 0; j < 3; j++) {
        if (j >= nct) break;
        wmma::store_matrix_sync(&Ss[(wr * 16) * SLD + (ct0 + j) * 16], sacc[j],
                                SLD, wmma::mem_row_major);
    }
    __syncthreads();

    // ---- phase 2: softmax. 4 threads per row, 24 cols each ----
    {
        const int row = tid >> 2, p = tid & 3;
        float* srow = &Ss[row * SLD];
        const int c0 = p * 24, c1 = c0 + 24;
        float mx = -1e30f;
        for (int c = c0; c < c1 && c < CTX_L; c++) mx = fmaxf(mx, srow[c]);
        mx = fmaxf(mx, __shfl_xor_sync(0xffffffffu, mx, 1));
        mx = fmaxf(mx, __shfl_xor_sync(0xffffffffu, mx, 2));
        float sum = 0.f;
        float ebuf[24];
#pragma unroll
        for (int i = 0; i < 24; i++) {
            int c = c0 + i;
            float e = (c < CTX_L) ? __expf(srow[c] - mx) : 0.f;
            ebuf[i] = e; sum += e;
        }
        sum += __shfl_xor_sync(0xffffffffu, sum, 1);
        sum += __shfl_xor_sync(0xffffffffu, sum, 2);
        const float inv = 1.f / sum;
#pragma unroll
        for (int i = 0; i < 24; i++) srow[c0 + i] = ebuf[i] * inv;
    }
    __syncthreads();

    // ---- phase 3: O = P @ V, two 32-col chunks of V ----
#pragma unroll
    for (int ch = 0; ch < 2; ch++) {
        for (int idx = tid; idx < CTX_L * 8; idx += 256) {
            int r = idx >> 3, c4 = (idx & 7) << 2;
            *(float4*)&Vs[r * VLD + c4] =
                *(const float4*)&g_V[((size_t)(b * CTX_L + r)) * INNER + h * DHEAD + ch * 32 + c4];
        }
        for (int idx = tid; idx < (LPAD - CTX_L) * 8; idx += 256) {
            int r = CTX_L + (idx >> 3), c4 = (idx & 7) << 2;
            *(float4*)&Vs[r * VLD + c4] = make_float4(0.f, 0.f, 0.f, 0.f);
        }
        __syncthreads();

        wmma::fragment<wmma::accumulator, 16, 16, 8, float> oacc;
        wmma::fill_fragment(oacc, 0.0f);
#pragma unroll
        for (int k = 0; k < LPAD / 8; k++) {
            wmma::fragment<wmma::matrix_a, 16, 16, 8, wmma::precision::tf32, wmma::row_major> af;
            wmma::fragment<wmma::matrix_b, 16, 16, 8, wmma::precision::tf32, wmma::row_major> bf;
            wmma::load_matrix_sync(af, &Ss[(wr * 16) * SLD + k * 8], SLD);
            wmma::load_matrix_sync(bf, &Vs[(k * 8) * VLD + wc * 16], VLD);
#pragma unroll
            for (int t = 0; t < af.num_elements; t++) af.x[t] = wmma::__float_to_tf32(af.x[t]);
#pragma unroll
            for (int t = 0; t < bf.num_elements; t++) bf.x[t] = wmma::__float_to_tf32(bf.x[t]);
            wmma::mma_sync(oacc, af, bf, oacc);
        }
        wmma::store_matrix_sync(
            &g_A[((size_t)(b * SEQ + s0 + wr * 16)) * INNER + h * DHEAD + ch * 32 + wc * 16],
            oacc, INNER, wmma::mem_row_major);
        __syncthreads();   // Vs reads done before next chunk overwrites
    }
}

// ---------------- launch ----------------
extern "C" void kernel_launch(void* const* d_in, const int* in_sizes, int n_in,
                              void* d_out, int out_size)
{
    const float* x       = (const float*)d_in[0];
    const float* context = (const float*)d_in[1];
    const float* Wq      = (const float*)d_in[2];
    const float* Wk      = (const float*)d_in[3];
    const float* Wv      = (const float*)d_in[4];
    const float* Wo      = (const float*)d_in[5];
    const float* bo      = (const float*)d_in[6];
    float* out = (float*)d_out;

    // dynamic-smem opt-in (host attribute; set on pre-capture call, persists)
    cudaFuncSetAttribute(gemm_q_fast, cudaFuncAttributeMaxDynamicSharedMemorySize, GEMM_SMEM_BYTES);
    cudaFuncSetAttribute(gemm_o_fast, cudaFuncAttributeMaxDynamicSharedMemorySize, GEMM_SMEM_BYTES);

    // Q = x @ Wq : (32768,1024)@(1024,512)
    gemm_q_fast<<<dim3(INNER / FBN, MX / FBM), 256, GEMM_SMEM_BYTES>>>(x, Wq);
    // K,V = context @ Wk/Wv : (616,768)@(768,512)
    gemm_k_kernel<<<dim3(INNER / GM_BN, (MC + GM_BM - 1) / GM_BM), 128>>>(context, Wk);
    gemm_v_kernel<<<dim3(INNER / GM_BN, (MC + GM_BM - 1) / GM_BM), 128>>>(context, Wv);
    // attention (tensor cores)
    attn_wmma_kernel<<<dim3(SEQ / BQ, HEADS, BATCH), 256>>>();
    // out = A @ Wo + bo : (32768,512)@(512,1024)
    gemm_o_fast<<<dim3(QDIM / FBN, MX / FBM), 256, GEMM_SMEM_BYTES>>>(Wo, bo, out);
}